// round 13
// baseline (speedup 1.0000x reference)
#include <cuda_runtime.h>
#include <stdint.h>

// Quantum 2x2 gate apply on qubit axis TARGET=5 of state (2,)^24 x (4,) f32.
//
// FINAL — converged measured optimum (reproduced 5x: R5/R7/R9/R11/R12).
//   one float4-pair per thread | flat grid, block=256 | 32-bit index math
//   default caching | 30 regs | DRAM 80.4-82.4%, 6.4-6.5 TB/s,
//   73.9-75.7us kernel, 81.7-82.2us bench (noise band on identical binary).
// Bound by the HBM3e mixed read/write (bus-turnaround) ceiling; traffic is
// the information-theoretic floor (512MB, every byte touched exactly once).
// All tuning axes bracketed and falsified:
//   per-thread width: f4 (best) / f4x2 MLP4 / v8 256-bit
//   block size: 128 / 256 (best) / 512
//   cache hints: default (best) / .cs loads / .cs stores
//   grid style: flat (best) / persistent grid-stride
//   pauli load: scalar x4 (best) / vectorized __ldg float4

static constexpr uint32_t SHIFT  = 18u;            // target stride in float4 units
static constexpr uint32_t NPAIRS = 1u << 23;       // 8,388,608 pairs

__global__ __launch_bounds__(256)
void gate_apply_kernel(const float4* __restrict__ state,
                       const float*  __restrict__ pauli,
                       float4* __restrict__ out)
{
    uint32_t v = blockIdx.x * blockDim.x + threadIdx.x;   // grid exactly covers NPAIRS

    const float p00 = pauli[0];
    const float p01 = pauli[1];
    const float p10 = pauli[2];
    const float p11 = pauli[3];

    uint32_t low  = v & ((1u << SHIFT) - 1u);
    uint32_t idx0 = ((v >> SHIFT) << (SHIFT + 1u)) | low;  // target bit = 0
    uint32_t idx1 = idx0 + (1u << SHIFT);                  // target bit = 1

    float4 s0 = state[idx0];
    float4 s1 = state[idx1];

    float4 o0, o1;
    o0.x = p00 * s0.x + p01 * s1.x;
    o0.y = p00 * s0.y + p01 * s1.y;
    o0.z = p00 * s0.z + p01 * s1.z;
    o0.w = p00 * s0.w + p01 * s1.w;

    o1.x = p10 * s0.x + p11 * s1.x;
    o1.y = p10 * s0.y + p11 * s1.y;
    o1.z = p10 * s0.z + p11 * s1.z;
    o1.w = p10 * s0.w + p11 * s1.w;

    out[idx0] = o0;
    out[idx1] = o1;
}

extern "C" void kernel_launch(void* const* d_in, const int* in_sizes, int n_in,
                              void* d_out, int out_size)
{
    const float4* state = (const float4*)d_in[0];
    const float*  pauli = (const float*)d_in[1];
    float4* out = (float4*)d_out;

    const int threads = 256;
    const unsigned blocks = NPAIRS / threads;   // 32768, exact cover
    gate_apply_kernel<<<blocks, threads>>>(state, pauli, out);
}

// round 14
// speedup vs baseline: 1.0008x; 1.0008x over previous
#include <cuda_runtime.h>
#include <stdint.h>

// Quantum 2x2 gate apply on qubit axis TARGET=5 of state (2,)^24 x (4,) f32.
//
// FINAL — converged measured optimum (reproduced 6x: R5/R7/R9/R11/R12/R13).
//   one float4-pair per thread | flat grid, block=256 | 32-bit index math
//   default caching | 30 regs
//   ncu 73.9-75.7us (capture noise) | bench 81.7-82.2us | DRAM 80.4-82.4%
// Bound by the HBM3e mixed read/write (bus-turnaround) ceiling at
// 6.4-6.5 TB/s realized; traffic is the information-theoretic floor
// (512MB, every byte touched exactly once). All tuning axes bracketed:
//   width f4/f4x2/v8 | block 128/256/512 | hints default/.cs-ld/.cs-st
//   grid flat/persistent | pauli scalar/vector — optimum interior on all.

static constexpr uint32_t SHIFT  = 18u;            // target stride in float4 units
static constexpr uint32_t NPAIRS = 1u << 23;       // 8,388,608 pairs

__global__ __launch_bounds__(256)
void gate_apply_kernel(const float4* __restrict__ state,
                       const float*  __restrict__ pauli,
                       float4* __restrict__ out)
{
    uint32_t v = blockIdx.x * blockDim.x + threadIdx.x;   // grid exactly covers NPAIRS

    const float p00 = pauli[0];
    const float p01 = pauli[1];
    const float p10 = pauli[2];
    const float p11 = pauli[3];

    uint32_t low  = v & ((1u << SHIFT) - 1u);
    uint32_t idx0 = ((v >> SHIFT) << (SHIFT + 1u)) | low;  // target bit = 0
    uint32_t idx1 = idx0 + (1u << SHIFT);                  // target bit = 1

    float4 s0 = state[idx0];
    float4 s1 = state[idx1];

    float4 o0, o1;
    o0.x = p00 * s0.x + p01 * s1.x;
    o0.y = p00 * s0.y + p01 * s1.y;
    o0.z = p00 * s0.z + p01 * s1.z;
    o0.w = p00 * s0.w + p01 * s1.w;

    o1.x = p10 * s0.x + p11 * s1.x;
    o1.y = p10 * s0.y + p11 * s1.y;
    o1.z = p10 * s0.z + p11 * s1.z;
    o1.w = p10 * s0.w + p11 * s1.w;

    out[idx0] = o0;
    out[idx1] = o1;
}

extern "C" void kernel_launch(void* const* d_in, const int* in_sizes, int n_in,
                              void* d_out, int out_size)
{
    const float4* state = (const float4*)d_in[0];
    const float*  pauli = (const float*)d_in[1];
    float4* out = (float4*)d_out;

    const int threads = 256;
    const unsigned blocks = NPAIRS / threads;   // 32768, exact cover
    gate_apply_kernel<<<blocks, threads>>>(state, pauli, out);
}

// round 15
// speedup vs baseline: 1.0012x; 1.0004x over previous
#include <cuda_runtime.h>
#include <stdint.h>

// Quantum 2x2 gate apply on qubit axis TARGET=5 of state (2,)^24 x (4,) f32.
//
// FINAL — converged measured optimum (reproduced 7x: R5/R7/R9/R11-R14).
//   one float4-pair per thread | flat grid, block=256 | 32-bit index math
//   default caching | 30 regs
//   ncu 73.9-75.7us (capture noise) | bench 81.7-82.2us | DRAM 80.4-82.4%
// Bound by the HBM3e mixed read/write (bus-turnaround) ceiling at
// 6.4-6.5 TB/s realized; traffic is the information-theoretic floor
// (512MB, every byte touched exactly once). All tuning axes bracketed:
//   width f4/f4x2/v8 | block 128/256/512 | hints default/.cs-ld/.cs-st
//   grid flat/persistent | pauli scalar/vector — optimum interior on all.

static constexpr uint32_t SHIFT  = 18u;            // target stride in float4 units
static constexpr uint32_t NPAIRS = 1u << 23;       // 8,388,608 pairs

__global__ __launch_bounds__(256)
void gate_apply_kernel(const float4* __restrict__ state,
                       const float*  __restrict__ pauli,
                       float4* __restrict__ out)
{
    uint32_t v = blockIdx.x * blockDim.x + threadIdx.x;   // grid exactly covers NPAIRS

    const float p00 = pauli[0];
    const float p01 = pauli[1];
    const float p10 = pauli[2];
    const float p11 = pauli[3];

    uint32_t low  = v & ((1u << SHIFT) - 1u);
    uint32_t idx0 = ((v >> SHIFT) << (SHIFT + 1u)) | low;  // target bit = 0
    uint32_t idx1 = idx0 + (1u << SHIFT);                  // target bit = 1

    float4 s0 = state[idx0];
    float4 s1 = state[idx1];

    float4 o0, o1;
    o0.x = p00 * s0.x + p01 * s1.x;
    o0.y = p00 * s0.y + p01 * s1.y;
    o0.z = p00 * s0.z + p01 * s1.z;
    o0.w = p00 * s0.w + p01 * s1.w;

    o1.x = p10 * s0.x + p11 * s1.x;
    o1.y = p10 * s0.y + p11 * s1.y;
    o1.z = p10 * s0.z + p11 * s1.z;
    o1.w = p10 * s0.w + p11 * s1.w;

    out[idx0] = o0;
    out[idx1] = o1;
}

extern "C" void kernel_launch(void* const* d_in, const int* in_sizes, int n_in,
                              void* d_out, int out_size)
{
    const float4* state = (const float4*)d_in[0];
    const float*  pauli = (const float*)d_in[1];
    float4* out = (float4*)d_out;

    const int threads = 256;
    const unsigned blocks = NPAIRS / threads;   // 32768, exact cover
    gate_apply_kernel<<<blocks, threads>>>(state, pauli, out);
}

// round 16
// speedup vs baseline: 1.0020x; 1.0008x over previous
#include <cuda_runtime.h>
#include <stdint.h>

// Quantum 2x2 gate apply on qubit axis TARGET=5 of state (2,)^24 x (4,) f32.
//
// FINAL — converged measured optimum (reproduced 8x: R5/R7/R9/R11-R15).
//   one float4-pair per thread | flat grid, block=256 | 32-bit index math
//   default caching | 30 regs
//   ncu 73.5-75.7us (capture noise) | bench 81.7-82.2us | DRAM 80.4-82.7%
// Bound by the HBM3e mixed read/write (bus-turnaround) ceiling at
// 6.4-6.56 TB/s realized; traffic is the information-theoretic floor
// (512MB, every byte touched exactly once). All tuning axes bracketed:
//   width f4/f4x2/v8 | block 128/256/512 | hints default/.cs-ld/.cs-st
//   grid flat/persistent | pauli scalar/vector — optimum interior on all.

static constexpr uint32_t SHIFT  = 18u;            // target stride in float4 units
static constexpr uint32_t NPAIRS = 1u << 23;       // 8,388,608 pairs

__global__ __launch_bounds__(256)
void gate_apply_kernel(const float4* __restrict__ state,
                       const float*  __restrict__ pauli,
                       float4* __restrict__ out)
{
    uint32_t v = blockIdx.x * blockDim.x + threadIdx.x;   // grid exactly covers NPAIRS

    const float p00 = pauli[0];
    const float p01 = pauli[1];
    const float p10 = pauli[2];
    const float p11 = pauli[3];

    uint32_t low  = v & ((1u << SHIFT) - 1u);
    uint32_t idx0 = ((v >> SHIFT) << (SHIFT + 1u)) | low;  // target bit = 0
    uint32_t idx1 = idx0 + (1u << SHIFT);                  // target bit = 1

    float4 s0 = state[idx0];
    float4 s1 = state[idx1];

    float4 o0, o1;
    o0.x = p00 * s0.x + p01 * s1.x;
    o0.y = p00 * s0.y + p01 * s1.y;
    o0.z = p00 * s0.z + p01 * s1.z;
    o0.w = p00 * s0.w + p01 * s1.w;

    o1.x = p10 * s0.x + p11 * s1.x;
    o1.y = p10 * s0.y + p11 * s1.y;
    o1.z = p10 * s0.z + p11 * s1.z;
    o1.w = p10 * s0.w + p11 * s1.w;

    out[idx0] = o0;
    out[idx1] = o1;
}

extern "C" void kernel_launch(void* const* d_in, const int* in_sizes, int n_in,
                              void* d_out, int out_size)
{
    const float4* state = (const float4*)d_in[0];
    const float*  pauli = (const float*)d_in[1];
    float4* out = (float4*)d_out;

    const int threads = 256;
    const unsigned blocks = NPAIRS / threads;   // 32768, exact cover
    gate_apply_kernel<<<blocks, threads>>>(state, pauli, out);
}

// round 17
// speedup vs baseline: 1.0039x; 1.0020x over previous
#include <cuda_runtime.h>
#include <stdint.h>

// Quantum 2x2 gate apply on qubit axis TARGET=5 of state (2,)^24 x (4,) f32.
//
// FINAL — converged measured optimum (reproduced 9x: R5/R7/R9/R11-R16).
//   one float4-pair per thread | flat grid, block=256 | 32-bit index math
//   default caching | 30 regs
//   ncu 73.5-75.7us (capture noise) | bench 81.7-82.2us | DRAM 80.4-82.7%
// Bound by the HBM3e mixed read/write (bus-turnaround) ceiling at
// 6.4-6.56 TB/s realized; traffic is the information-theoretic floor
// (512MB, every byte touched exactly once). All tuning axes bracketed:
//   width f4/f4x2/v8 | block 128/256/512 | hints default/.cs-ld/.cs-st
//   grid flat/persistent | pauli scalar/vector — optimum interior on all.

static constexpr uint32_t SHIFT  = 18u;            // target stride in float4 units
static constexpr uint32_t NPAIRS = 1u << 23;       // 8,388,608 pairs

__global__ __launch_bounds__(256)
void gate_apply_kernel(const float4* __restrict__ state,
                       const float*  __restrict__ pauli,
                       float4* __restrict__ out)
{
    uint32_t v = blockIdx.x * blockDim.x + threadIdx.x;   // grid exactly covers NPAIRS

    const float p00 = pauli[0];
    const float p01 = pauli[1];
    const float p10 = pauli[2];
    const float p11 = pauli[3];

    uint32_t low  = v & ((1u << SHIFT) - 1u);
    uint32_t idx0 = ((v >> SHIFT) << (SHIFT + 1u)) | low;  // target bit = 0
    uint32_t idx1 = idx0 + (1u << SHIFT);                  // target bit = 1

    float4 s0 = state[idx0];
    float4 s1 = state[idx1];

    float4 o0, o1;
    o0.x = p00 * s0.x + p01 * s1.x;
    o0.y = p00 * s0.y + p01 * s1.y;
    o0.z = p00 * s0.z + p01 * s1.z;
    o0.w = p00 * s0.w + p01 * s1.w;

    o1.x = p10 * s0.x + p11 * s1.x;
    o1.y = p10 * s0.y + p11 * s1.y;
    o1.z = p10 * s0.z + p11 * s1.z;
    o1.w = p10 * s0.w + p11 * s1.w;

    out[idx0] = o0;
    out[idx1] = o1;
}

extern "C" void kernel_launch(void* const* d_in, const int* in_sizes, int n_in,
                              void* d_out, int out_size)
{
    const float4* state = (const float4*)d_in[0];
    const float*  pauli = (const float*)d_in[1];
    float4* out = (float4*)d_out;

    const int threads = 256;
    const unsigned blocks = NPAIRS / threads;   // 32768, exact cover
    gate_apply_kernel<<<blocks, threads>>>(state, pauli, out);
}